// round 14
// baseline (speedup 1.0000x reference)
#include <cuda_runtime.h>
#include <cstdint>

// ---------------------------------------------------------------------------
// ANI AEV scatter build, round 11 (resubmit x2 — R12/R13 were infra timeouts):
//  L1tex-wavefront reduction (scatter measured txn-rate-bound at ~1 wf/cyc/SM):
//  - angular pair record packed to ONE 16B load: {rx,ry,rz, i|si<<17|sj<<20},
//    d recomputed as sqrtf(dot) (was 2 LDGs / 4 lane-txns per pair access)
//  - radial per-pair record {i|si<<17, j|sj<<17, d} precomputed in prep ->
//    radial reads 1 coalesced 16B instead of 2 random gathers + 3 loads
//  - thresholds unchanged: radial dist<0.066, angular arg<7.0
// ---------------------------------------------------------------------------

#define S_       7
#define NRBF_    16
#define NPAIRS_  28
#define SUB_     32
#define NA_      8
#define NZ_      4
#define RC_      0.51f
#define RMIN_    0.08f
#define RCA_     0.35f
#define RAMIN_   0.08f
#define ETA_R_   1970.0f
#define ETA_A_   1250.0f
#define ZETA_    14.1f
#define ROW_     1008      // S_*NRBF_ + NPAIRS_*SUB_
#define ANG_OFF_ 112       // S_*NRBF_
#define PI_      3.14159265358979323846f
#define PA_MAX_  200000
#define P_MAX_   1000000

#define THREADS_ 256

// angular: one 16B record per pair: {rx, ry, rz, bits(i | si<<17 | sj<<20)}
__device__ float4 g_ang[PA_MAX_];       // 3.2 MB
// radial: one 16B record per pair: {i|si<<17, j|sj<<17, d_bits, pad}
__device__ int4   g_rad[P_MAX_];        // 16 MB

// sm_90+ vector reduction: one instruction adds 4 contiguous fp32 in L2.
__device__ __forceinline__ void red_add_v4(float* addr, float a, float b, float c, float d) {
    asm volatile("red.global.add.v4.f32 [%0], {%1, %2, %3, %4};"
                 :: "l"(addr), "f"(a), "f"(b), "f"(c), "f"(d)
                 : "memory");
}

// ---------------------------------------------------------------------------
// Prep: gathers + packing for BOTH scatter phases (absorbs the random atom
// gathers into this latency-bound kernel, off the saturated scatter).
// ---------------------------------------------------------------------------
__global__ void __launch_bounds__(THREADS_)
prep_kernel(const int* __restrict__ atom_index,
            const int* __restrict__ pair_idx,   // [2, P]
            const float* __restrict__ d_ij,     // [P]
            const float* __restrict__ r_ij,     // [P, 3]
            int P, int PA)
{
    int p = blockIdx.x * THREADS_ + threadIdx.x;
    if (p >= P) return;
    int i = pair_idx[p];
    int j = pair_idx[P + p];
    int si = atom_index[i];
    int sj = atom_index[j];
    float d = d_ij[p];
    g_rad[p] = make_int4(i | (si << 17), j | (sj << 17), __float_as_int(d), 0);
    if (p < PA) {
        float rx = r_ij[3*p + 0], ry = r_ij[3*p + 1], rz = r_ij[3*p + 2];
        int bits = i | (si << 17) | (sj << 20);
        g_ang[p] = make_float4(rx, ry, rz, __int_as_float(bits));
    }
}

// ---------------------------------------------------------------------------
// Radial part: one thread per pair, single coalesced 16B input record.
// ---------------------------------------------------------------------------
__device__ __forceinline__ void do_radial(float* __restrict__ out, int P, int p)
{
    if (p >= P) return;

    int4 rec = g_rad[p];
    int   i  = rec.x & 0x1FFFF;
    int   si = rec.x >> 17;
    int   j  = rec.y & 0x1FFFF;
    int   sj = rec.y >> 17;
    float d  = __int_as_float(rec.z);

    float fc = (d < RC_) ? (0.5f * __cosf(PI_ * d * (1.0f / RC_)) + 0.5f) : 0.0f;
    float amp = 0.25f * fc;

    const float step = (RC_ - RMIN_) / (float)NRBF_;   // 0.026875

    float* r0 = out + (long long)i * ROW_ + sj * NRBF_;
    float* r1 = out + (long long)j * ROW_ + si * NRBF_;

#pragma unroll
    for (int q = 0; q < 4; q++) {
        float lo = RMIN_ + (float)(4*q) * step;
        float hi = lo + 3.0f * step;
        float dist = fmaxf(fmaxf(lo - d, d - hi), 0.0f);
        // exp(-1970 * 0.066^2) ~= 1.9e-4: all 4 terms negligible beyond
        if (dist < 0.066f) {
            float x0 = d - lo;
            float x1 = x0 - step;
            float x2 = x1 - step;
            float x3 = x2 - step;
            float t0 = amp * __expf(-ETA_R_ * x0 * x0);
            float t1 = amp * __expf(-ETA_R_ * x1 * x1);
            float t2 = amp * __expf(-ETA_R_ * x2 * x2);
            float t3 = amp * __expf(-ETA_R_ * x3 * x3);
            red_add_v4(r0 + 4*q, t0, t1, t2, t3);
            red_add_v4(r1 + 4*q, t0, t1, t2, t3);
        }
    }
}

// ---------------------------------------------------------------------------
// Angular part: one thread per triple, ONE 16B random load per pair access.
// d12 recomputed from the vector (norm is sign-invariant, matches reference
// to ~1e-7). sign/species derived from comparing central vs endpoint i.
// ---------------------------------------------------------------------------
__device__ __forceinline__ void do_angular(const int* __restrict__ central,
                                           const int* __restrict__ pidx12,
                                           float* __restrict__ out,
                                           int T, int tf)
{
    if (tf >= T) return;
    int t = T - 1 - tf;   // reverse traversal (matches measured baseline)

    int c  = central[t];
    int p0 = pidx12[t];
    int p1 = pidx12[T + t];

    float4 a0 = g_ang[p0];
    float4 a1 = g_ang[p1];
    int b0 = __float_as_int(a0.w);
    int b1 = __float_as_int(a1.w);

    int i0 = b0 & 0x1FFFF;
    int i1 = b1 & 0x1FFFF;
    bool ci0 = (c == i0);           // sign12[0] == +1
    bool ci1 = (c == i1);           // sign12[1] == +1

    // neighbor species: +1 -> species of j endpoint (bits 20..22),
    //                   -1 -> species of i endpoint (bits 17..19)
    int sp0 = (ci0 ? (b0 >> 20) : (b0 >> 17)) & 7;
    int sp1 = (ci1 ? (b1 >> 20) : (b1 >> 17)) & 7;

    float n0 = a0.x*a0.x + a0.y*a0.y + a0.z*a0.z;
    float n1 = a1.x*a1.x + a1.y*a1.y + a1.z*a1.z;
    float d0 = sqrtf(n0);
    float d1 = sqrtf(n1);
    float dot = a0.x*a1.x + a0.y*a1.y + a0.z*a1.z;
    float sgn = (ci0 == ci1) ? 1.0f : -1.0f;   // product of the two signs

    float cos_a = __fdividef(0.95f * sgn * dot, d0 * d1);
    float sin_a = sqrtf(fmaxf(1.0f - cos_a * cos_a, 0.0f));

    float fc0 = (d0 < RCA_) ? (0.5f * __cosf(PI_ * d0 * (1.0f / RCA_)) + 0.5f) : 0.0f;
    float fc1 = (d1 < RCA_) ? (0.5f * __cosf(PI_ * d1 * (1.0f / RCA_)) + 0.5f) : 0.0f;
    float fcp = 2.0f * fc0 * fc1;
    float davg = 0.5f * (d0 + d1);

    int a = min(sp0, sp1), b = max(sp0, sp1);
    int triu = a * S_ - (a * (a - 1)) / 2 + (b - a);

    // f1[z] = ((1 + cos(angle - shfz_z)) / 2)^ZETA,  shfz = (z+0.5)*pi/4
    const float cz0 =  0.9238795325112867f, sz0 = 0.3826834323650898f;
    const float cz1 =  0.3826834323650898f, sz1 = 0.9238795325112867f;
    const float cz2 = -0.3826834323650898f, sz2 = 0.9238795325112867f;
    const float cz3 = -0.9238795325112867f, sz3 = 0.3826834323650898f;

    float f10 = __powf(fmaxf(0.5f * (1.0f + cos_a * cz0 + sin_a * sz0), 0.0f), ZETA_);
    float f11 = __powf(fmaxf(0.5f * (1.0f + cos_a * cz1 + sin_a * sz1), 0.0f), ZETA_);
    float f12 = __powf(fmaxf(0.5f * (1.0f + cos_a * cz2 + sin_a * sz2), 0.0f), ZETA_);
    float f13 = __powf(fmaxf(0.5f * (1.0f + cos_a * cz3 + sin_a * sz3), 0.0f), ZETA_);

    float* dst = out + (long long)c * ROW_ + ANG_OFF_ + triu * SUB_;

    const float step_a = (RCA_ - RAMIN_) / (float)NA_;   // 0.03375
#pragma unroll
    for (int k = 0; k < NA_; k++) {
        float y = davg - (RAMIN_ + (float)k * step_a);
        float arg = ETA_A_ * y * y;
        // exp(-7) ~= 9.1e-4: negligible below threshold
        if (arg < 7.0f) {
            float f2 = fcp * __expf(-arg);
            red_add_v4(dst + 4*k, f2 * f10, f2 * f11, f2 * f12, f2 * f13);
        }
    }
}

__global__ void __launch_bounds__(THREADS_)
scatter_kernel(const int* __restrict__ central,
               const int* __restrict__ pidx12,
               float* __restrict__ out,
               int P, int T, int ang_blocks)
{
    int b = (int)blockIdx.x;
    if (b < ang_blocks) {
        do_angular(central, pidx12, out, T, b * THREADS_ + (int)threadIdx.x);
    } else {
        do_radial(out, P, (b - ang_blocks) * THREADS_ + (int)threadIdx.x);
    }
}

// ---------------------------------------------------------------------------
// Launch.  Inputs (metadata order):
//  0: atom_index int32[N]  1: pair_indices int32[2,P]  2: d_ij f32[P,1]
//  3: r_ij f32[P,3]  4: central int32[T]  5: pair_index12 int32[2,T]
//  6: sign12 int32[2,T]      Output: f32 [N, 1008]
// ---------------------------------------------------------------------------
extern "C" void kernel_launch(void* const* d_in, const int* in_sizes, int n_in,
                              void* d_out, int out_size)
{
    const int*   atom_index = (const int*)d_in[0];
    const int*   pair_idx   = (const int*)d_in[1];
    const float* d_ij       = (const float*)d_in[2];
    const float* r_ij       = (const float*)d_in[3];
    const int*   central    = (const int*)d_in[4];
    const int*   pidx12     = (const int*)d_in[5];
    float*       out        = (float*)d_out;

    int P = in_sizes[2];
    int T = in_sizes[4];
    if (P > P_MAX_) P = P_MAX_;
    int PA = P < PA_MAX_ ? P : PA_MAX_;

    cudaMemsetAsync(out, 0, (size_t)out_size * sizeof(float));

    prep_kernel<<<(P + THREADS_ - 1) / THREADS_, THREADS_>>>(
        atom_index, pair_idx, d_ij, r_ij, P, PA);

    {
        int ang_blocks = (T + THREADS_ - 1) / THREADS_;
        int rad_blocks = (P + THREADS_ - 1) / THREADS_;
        scatter_kernel<<<ang_blocks + rad_blocks, THREADS_>>>(
            central, pidx12, out, P, T, ang_blocks);
    }
}

// round 17
// speedup vs baseline: 1.0875x; 1.0875x over previous
#include <cuda_runtime.h>
#include <cstdint>

// ---------------------------------------------------------------------------
// ANI AEV scatter build, round 14 (resubmit x2 — R15/R16 were infra timeouts):
//  - scatter is at its LTS-atomic-service floor (~71us, proven over 3 rounds);
//    this round attacks the OTHER 42us:
//  - revert R11 radial prep-packing (net regression): radial reads inputs
//    directly; prep packs only the 200K angular records
//  - fused zero+prep kernel: 12288 zero blocks w/ 32-bit indexed float4
//    stores (fixes R2's slow zero) + 782 prep blocks riding in its shadow
//  - scatter unchanged from measured R11/R7 best parts
// ---------------------------------------------------------------------------

#define S_       7
#define NRBF_    16
#define NPAIRS_  28
#define SUB_     32
#define NA_      8
#define NZ_      4
#define RC_      0.51f
#define RMIN_    0.08f
#define RCA_     0.35f
#define RAMIN_   0.08f
#define ETA_R_   1970.0f
#define ETA_A_   1250.0f
#define ZETA_    14.1f
#define ROW_     1008      // S_*NRBF_ + NPAIRS_*SUB_
#define ANG_OFF_ 112       // S_*NRBF_
#define PI_      3.14159265358979323846f
#define PA_MAX_  200000

#define THREADS_ 256
#define ZERO_BLOCKS_ 12288

// angular: one 16B record per pair: {rx, ry, rz, bits(i | si<<17 | sj<<20)}
__device__ float4 g_ang[PA_MAX_];       // 3.2 MB

// sm_90+ vector reduction: one instruction adds 4 contiguous fp32 in L2.
__device__ __forceinline__ void red_add_v4(float* addr, float a, float b, float c, float d) {
    asm volatile("red.global.add.v4.f32 [%0], {%1, %2, %3, %4};"
                 :: "l"(addr), "f"(a), "f"(b), "f"(c), "f"(d)
                 : "memory");
}

// ---------------------------------------------------------------------------
// Phase 1: blocks [0, prep_blocks) pack angular records; the rest zero `out`.
// Zero path: 32-bit indexing, float4 stores, 3.1M threads x 16 iterations.
// ---------------------------------------------------------------------------
__global__ void __launch_bounds__(THREADS_)
zero_prep_kernel(const int* __restrict__ atom_index,
                 const int* __restrict__ pair_idx,   // [2, P]
                 const float* __restrict__ r_ij,     // [P, 3]
                 float* __restrict__ out,
                 int P, int PA, int prep_blocks, unsigned n4)
{
    if ((int)blockIdx.x < prep_blocks) {
        int p = blockIdx.x * THREADS_ + threadIdx.x;
        if (p >= PA) return;
        float rx = r_ij[3*p + 0], ry = r_ij[3*p + 1], rz = r_ij[3*p + 2];
        int i = pair_idx[p];
        int j = pair_idx[P + p];
        int si = atom_index[i];
        int sj = atom_index[j];
        int bits = i | (si << 17) | (sj << 20);
        g_ang[p] = make_float4(rx, ry, rz, __int_as_float(bits));
    } else {
        unsigned zb   = blockIdx.x - prep_blocks;
        unsigned tid  = zb * THREADS_ + threadIdx.x;
        unsigned nthr = (gridDim.x - prep_blocks) * THREADS_;
        float4* o4 = (float4*)out;
        float4 z = make_float4(0.f, 0.f, 0.f, 0.f);
        for (unsigned q = tid; q < n4; q += nthr)
            o4[q] = z;
    }
}

// ---------------------------------------------------------------------------
// Radial part: one thread per pair, direct input reads (R7 style, measured
// better than prep-packed R11).
// ---------------------------------------------------------------------------
__device__ __forceinline__ void do_radial(const int* __restrict__ atom_index,
                                          const int* __restrict__ pair_idx,
                                          const float* __restrict__ d_ij,
                                          float* __restrict__ out,
                                          int P, int p)
{
    if (p >= P) return;

    float d  = d_ij[p];
    int   i  = pair_idx[p];
    int   j  = pair_idx[P + p];
    int   si = atom_index[i];
    int   sj = atom_index[j];

    float fc = (d < RC_) ? (0.5f * __cosf(PI_ * d * (1.0f / RC_)) + 0.5f) : 0.0f;
    float amp = 0.25f * fc;

    const float step = (RC_ - RMIN_) / (float)NRBF_;   // 0.026875

    float* r0 = out + (long long)i * ROW_ + sj * NRBF_;
    float* r1 = out + (long long)j * ROW_ + si * NRBF_;

#pragma unroll
    for (int q = 0; q < 4; q++) {
        float lo = RMIN_ + (float)(4*q) * step;
        float hi = lo + 3.0f * step;
        float dist = fmaxf(fmaxf(lo - d, d - hi), 0.0f);
        // exp(-1970 * 0.066^2) ~= 1.9e-4: all 4 terms negligible beyond
        if (dist < 0.066f) {
            float x0 = d - lo;
            float x1 = x0 - step;
            float x2 = x1 - step;
            float x3 = x2 - step;
            float t0 = amp * __expf(-ETA_R_ * x0 * x0);
            float t1 = amp * __expf(-ETA_R_ * x1 * x1);
            float t2 = amp * __expf(-ETA_R_ * x2 * x2);
            float t3 = amp * __expf(-ETA_R_ * x3 * x3);
            red_add_v4(r0 + 4*q, t0, t1, t2, t3);
            red_add_v4(r1 + 4*q, t0, t1, t2, t3);
        }
    }
}

// ---------------------------------------------------------------------------
// Angular part: one thread per triple, ONE 16B random load per pair access
// (measured R11). d12 recomputed from the vector; sign/species from central
// comparison.
// ---------------------------------------------------------------------------
__device__ __forceinline__ void do_angular(const int* __restrict__ central,
                                           const int* __restrict__ pidx12,
                                           float* __restrict__ out,
                                           int T, int tf)
{
    if (tf >= T) return;
    int t = T - 1 - tf;   // reverse traversal (matches measured baseline)

    int c  = central[t];
    int p0 = pidx12[t];
    int p1 = pidx12[T + t];

    float4 a0 = g_ang[p0];
    float4 a1 = g_ang[p1];
    int b0 = __float_as_int(a0.w);
    int b1 = __float_as_int(a1.w);

    int i0 = b0 & 0x1FFFF;
    int i1 = b1 & 0x1FFFF;
    bool ci0 = (c == i0);           // sign12[0] == +1
    bool ci1 = (c == i1);           // sign12[1] == +1

    int sp0 = (ci0 ? (b0 >> 20) : (b0 >> 17)) & 7;
    int sp1 = (ci1 ? (b1 >> 20) : (b1 >> 17)) & 7;

    float n0 = a0.x*a0.x + a0.y*a0.y + a0.z*a0.z;
    float n1 = a1.x*a1.x + a1.y*a1.y + a1.z*a1.z;
    float d0 = sqrtf(n0);
    float d1 = sqrtf(n1);
    float dot = a0.x*a1.x + a0.y*a1.y + a0.z*a1.z;
    float sgn = (ci0 == ci1) ? 1.0f : -1.0f;

    float cos_a = __fdividef(0.95f * sgn * dot, d0 * d1);
    float sin_a = sqrtf(fmaxf(1.0f - cos_a * cos_a, 0.0f));

    float fc0 = (d0 < RCA_) ? (0.5f * __cosf(PI_ * d0 * (1.0f / RCA_)) + 0.5f) : 0.0f;
    float fc1 = (d1 < RCA_) ? (0.5f * __cosf(PI_ * d1 * (1.0f / RCA_)) + 0.5f) : 0.0f;
    float fcp = 2.0f * fc0 * fc1;
    float davg = 0.5f * (d0 + d1);

    int a = min(sp0, sp1), b = max(sp0, sp1);
    int triu = a * S_ - (a * (a - 1)) / 2 + (b - a);

    const float cz0 =  0.9238795325112867f, sz0 = 0.3826834323650898f;
    const float cz1 =  0.3826834323650898f, sz1 = 0.9238795325112867f;
    const float cz2 = -0.3826834323650898f, sz2 = 0.9238795325112867f;
    const float cz3 = -0.9238795325112867f, sz3 = 0.3826834323650898f;

    float f10 = __powf(fmaxf(0.5f * (1.0f + cos_a * cz0 + sin_a * sz0), 0.0f), ZETA_);
    float f11 = __powf(fmaxf(0.5f * (1.0f + cos_a * cz1 + sin_a * sz1), 0.0f), ZETA_);
    float f12 = __powf(fmaxf(0.5f * (1.0f + cos_a * cz2 + sin_a * sz2), 0.0f), ZETA_);
    float f13 = __powf(fmaxf(0.5f * (1.0f + cos_a * cz3 + sin_a * sz3), 0.0f), ZETA_);

    float* dst = out + (long long)c * ROW_ + ANG_OFF_ + triu * SUB_;

    const float step_a = (RCA_ - RAMIN_) / (float)NA_;   // 0.03375
#pragma unroll
    for (int k = 0; k < NA_; k++) {
        float y = davg - (RAMIN_ + (float)k * step_a);
        float arg = ETA_A_ * y * y;
        // exp(-7) ~= 9.1e-4: negligible below threshold
        if (arg < 7.0f) {
            float f2 = fcp * __expf(-arg);
            red_add_v4(dst + 4*k, f2 * f10, f2 * f11, f2 * f12, f2 * f13);
        }
    }
}

__global__ void __launch_bounds__(THREADS_)
scatter_kernel(const int* __restrict__ atom_index,
               const int* __restrict__ pair_idx,
               const float* __restrict__ d_ij,
               const int* __restrict__ central,
               const int* __restrict__ pidx12,
               float* __restrict__ out,
               int P, int T, int ang_blocks)
{
    int b = (int)blockIdx.x;
    if (b < ang_blocks) {
        do_angular(central, pidx12, out, T, b * THREADS_ + (int)threadIdx.x);
    } else {
        do_radial(atom_index, pair_idx, d_ij, out, P,
                  (b - ang_blocks) * THREADS_ + (int)threadIdx.x);
    }
}

// ---------------------------------------------------------------------------
// Launch.  Inputs (metadata order):
//  0: atom_index int32[N]  1: pair_indices int32[2,P]  2: d_ij f32[P,1]
//  3: r_ij f32[P,3]  4: central int32[T]  5: pair_index12 int32[2,T]
//  6: sign12 int32[2,T]      Output: f32 [N, 1008]
// ---------------------------------------------------------------------------
extern "C" void kernel_launch(void* const* d_in, const int* in_sizes, int n_in,
                              void* d_out, int out_size)
{
    const int*   atom_index = (const int*)d_in[0];
    const int*   pair_idx   = (const int*)d_in[1];
    const float* d_ij       = (const float*)d_in[2];
    const float* r_ij       = (const float*)d_in[3];
    const int*   central    = (const int*)d_in[4];
    const int*   pidx12     = (const int*)d_in[5];
    float*       out        = (float*)d_out;

    int P = in_sizes[2];
    int T = in_sizes[4];
    int PA = P < PA_MAX_ ? P : PA_MAX_;

    {
        int prep_blocks = (PA + THREADS_ - 1) / THREADS_;
        unsigned n4 = (unsigned)(out_size >> 2);   // float4 count
        zero_prep_kernel<<<prep_blocks + ZERO_BLOCKS_, THREADS_>>>(
            atom_index, pair_idx, r_ij, out, P, PA, prep_blocks, n4);
    }
    {
        int ang_blocks = (T + THREADS_ - 1) / THREADS_;
        int rad_blocks = (P + THREADS_ - 1) / THREADS_;
        scatter_kernel<<<ang_blocks + rad_blocks, THREADS_>>>(
            atom_index, pair_idx, d_ij, central, pidx12, out,
            P, T, ang_blocks);
    }
}